// round 8
// baseline (speedup 1.0000x reference)
#include <cuda_runtime.h>
#include <cuda_fp16.h>
#include <math.h>
#include <stdint.h>

// Problem dims (fixed)
#define BATCH 4
#define SEQ   4096
#define DIM   1024
#define HEADS 16
#define DFF   4096
#define ROWS  16384
#define QKVW  3072

// ---------------------------------------------------------------------------
// Scratch (device globals; no runtime allocation allowed)
// ---------------------------------------------------------------------------
__device__ __half g_h1  [ROWS*(size_t)DIM];
__device__ __half g_qkv [ROWS*(size_t)QKVW];
__device__ __half g_ao  [ROWS*(size_t)DIM];
__device__ float  g_x2  [ROWS*(size_t)DIM];
__device__ __half g_h2  [ROWS*(size_t)DIM];
__device__ float  g_dot [BATCH*HEADS*(size_t)SEQ];
__device__ __half g_act [ROWS*(size_t)DFF];
__device__ __half g_wqkvT[(size_t)QKVW*DIM];   // [3072][1024] K-major (N rows)
__device__ __half g_woT [(size_t)DIM*DIM];
__device__ __half g_w1T [(size_t)DFF*DIM];
__device__ __half g_w2T [(size_t)DIM*DFF];

// ---------------------------------------------------------------------------
// Helpers
// ---------------------------------------------------------------------------
__device__ __forceinline__ float gelu_exact(float x) {
    return 0.5f * x * (1.0f + erff(x * 0.70710678118654752f));
}
__device__ __forceinline__ uint32_t smem_u32(const void* p) {
    uint32_t a;
    asm("{ .reg .u64 t; cvta.to.shared.u64 t, %1; cvt.u32.u64 %0, t; }"
        : "=r"(a) : "l"(p));
    return a;
}
__device__ __forceinline__ void cp16(uint32_t dst, const void* src) {
    asm volatile("cp.async.cg.shared.global [%0], [%1], 16;" :: "r"(dst), "l"(src));
}
__device__ __forceinline__ void cp_commit() {
    asm volatile("cp.async.commit_group;" ::: "memory");
}
#define LDMX4(r0, r1, r2, r3, addr)                                           \
    asm volatile("ldmatrix.sync.aligned.m8n8.x4.shared.b16 {%0,%1,%2,%3}, [%4];" \
        : "=r"(r0), "=r"(r1), "=r"(r2), "=r"(r3) : "r"(addr))

// smem row: 32 k-halves data + 8 pad halves -> stride 40 halves (80B).
// Rows r within an 8-row ldmatrix tile hit banks (r*20)%32: all distinct.
#define OP_B     10240                     // bytes per operand tile (128*80)
#define STAGE_B  (2*OP_B)                  // 20480
#define STAGES   5
#define SMEM_DYN (STAGES*STAGE_B)          // 102400

// ---------------------------------------------------------------------------
// FP16 tensor-core GEMM: C[M,N] = A[M,K] @ Bt[N,K]^T  (A,Bt fp16)
//  EPI 0: store half           (C = __half*)
//  EPI 1: float store +res+bias (C = float*, res fp32)
//  EPI 2: half store gelu(+bias)
// CTA 128x128, 128 threads (4 warps 2x2, warp tile 64x64), k-chunk 32,
// 5-stage cp.async pipeline (R5 two-sync loop), all chunk fragments loaded
// up-front so MMAs never stall on in-flight LDSM.
// ---------------------------------------------------------------------------
template <int EPI>
__global__ __launch_bounds__(128, 2) void gemm_fp16(
    const __half* __restrict__ A, const __half* __restrict__ Bt,
    void* __restrict__ Cv, const float* __restrict__ res,
    const float* __restrict__ bias, int M, int N, int K)
{
    extern __shared__ char smc[];
    const uint32_t smb = smem_u32(smc);

    const int tid  = threadIdx.x;
    const int lane = tid & 31;
    const int wid  = tid >> 5;
    const int wm   = wid >> 1;
    const int wn   = wid & 1;
    const int g    = lane >> 2;
    const int t    = lane & 3;
    const int m0   = blockIdx.y << 7;
    const int n0   = blockIdx.x << 7;

    // ldmatrix per-lane base offsets (bytes within stage)
    const uint32_t aoff =
        (uint32_t)(((wm * 64 + (lane & 7) + 8 * ((lane >> 3) & 1)) * 40 +
                    8 * (lane >> 4)) * 2);
    const uint32_t boff =
        (uint32_t)(OP_B + (((wn * 64 + (lane & 7) + 8 * (lane >> 4)) * 40 +
                            8 * ((lane >> 3) & 1)) * 2));

    // staging: per operand 512 granules of 16B; 4 per thread
    uint32_t sA[4], sB[4];
    const __half* gA[4];
    const __half* gB[4];
#pragma unroll
    for (int j = 0; j < 4; j++) {
        const int gid = j * 128 + tid;
        const int row = gid >> 2, c = gid & 3;
        sA[j] = (uint32_t)(row * 80 + c * 16);
        sB[j] = (uint32_t)(OP_B + row * 80 + c * 16);
        gA[j] = A  + (size_t)(m0 + row) * K + c * 8;
        gB[j] = Bt + (size_t)(n0 + row) * K + c * 8;
    }

    float acc[4][8][4];
#pragma unroll
    for (int i = 0; i < 4; i++)
#pragma unroll
        for (int j = 0; j < 8; j++)
#pragma unroll
            for (int r = 0; r < 4; r++) acc[i][j][r] = 0.f;

    const int KT = K >> 5;

    // prologue: fill all STAGES slots
#pragma unroll
    for (int s = 0; s < STAGES; s++) {
        const uint32_t base = smb + s * STAGE_B;
        const int ko = s * 32;
#pragma unroll
        for (int j = 0; j < 4; j++) {
            cp16(base + sA[j], gA[j] + ko);
            cp16(base + sB[j], gB[j] + ko);
        }
        cp_commit();
    }

    for (int kt = 0; kt < KT; kt++) {
        asm volatile("cp.async.wait_group %0;" :: "n"(STAGES - 1) : "memory");
        __syncthreads();

        // compute chunk kt: load ALL fragments first, then all MMAs
        const uint32_t stg = smb + (kt % STAGES) * STAGE_B;
        uint32_t af[2][4][4], bf[2][8][2];
#pragma unroll
        for (int kc = 0; kc < 2; kc++) {
            const uint32_t kb = kc * 32;            // 16 halves
#pragma unroll
            for (int i = 0; i < 4; i++)
                LDMX4(af[kc][i][0], af[kc][i][1], af[kc][i][2], af[kc][i][3],
                      stg + aoff + i * 1280 + kb);
#pragma unroll
            for (int jj = 0; jj < 4; jj++)
                LDMX4(bf[kc][2 * jj][0], bf[kc][2 * jj][1],
                      bf[kc][2 * jj + 1][0], bf[kc][2 * jj + 1][1],
                      stg + boff + jj * 1280 + kb);
        }
#pragma unroll
        for (int kc = 0; kc < 2; kc++)
#pragma unroll
            for (int i = 0; i < 4; i++)
#pragma unroll
                for (int j = 0; j < 8; j++) {
                    asm volatile(
                        "mma.sync.aligned.m16n8k16.row.col.f32.f16.f16.f32 "
                        "{%0,%1,%2,%3}, {%4,%5,%6,%7}, {%8,%9}, {%0,%1,%2,%3};"
                        : "+f"(acc[i][j][0]), "+f"(acc[i][j][1]),
                          "+f"(acc[i][j][2]), "+f"(acc[i][j][3])
                        : "r"(af[kc][i][0]), "r"(af[kc][i][1]),
                          "r"(af[kc][i][2]), "r"(af[kc][i][3]),
                          "r"(bf[kc][j][0]), "r"(bf[kc][j][1]));
                }
        __syncthreads();

        // prefetch chunk kt+STAGES into the slot just consumed
        const int nk = kt + STAGES;
        if (nk < KT) {
            const uint32_t base = smb + (nk % STAGES) * STAGE_B;
            const int ko = nk * 32;
#pragma unroll
            for (int j = 0; j < 4; j++) {
                cp16(base + sA[j], gA[j] + ko);
                cp16(base + sB[j], gB[j] + ko);
            }
        }
        cp_commit();
    }

    // epilogue
#pragma unroll
    for (int j = 0; j < 8; j++) {
        const int col = n0 + wn * 64 + j * 8 + t * 2;
        float2 bv = make_float2(0.f, 0.f);
        if (EPI != 0) bv = *(const float2*)&bias[col];
#pragma unroll
        for (int i = 0; i < 4; i++) {
            const int row0 = m0 + wm * 64 + i * 16 + g;
#pragma unroll
            for (int h = 0; h < 2; h++) {
                const int r = row0 + 8 * h;
                const float a = acc[i][j][2 * h + 0];
                const float b = acc[i][j][2 * h + 1];
                if (EPI == 0) {
                    *(__half2*)((__half*)Cv + (size_t)r * N + col) =
                        __floats2half2_rn(a, b);
                } else if (EPI == 1) {
                    const float2 rv = *(const float2*)&res[(size_t)r * N + col];
                    float2 o;
                    o.x = a + rv.x + bv.x;
                    o.y = b + rv.y + bv.y;
                    *(float2*)((float*)Cv + (size_t)r * N + col) = o;
                } else {
                    *(__half2*)((__half*)Cv + (size_t)r * N + col) =
                        __floats2half2_rn(gelu_exact(a + bv.x),
                                          gelu_exact(b + bv.y));
                }
            }
        }
    }
}

// ---------------------------------------------------------------------------
// All 6 weight transposes in ONE launch. Tile t:
//   [0,4096)      4 square jobs wq/wk/wv/wo  (1024x1024, 32x32 grids)
//   [4096,8192)   w1 [1024][4096] -> w1T
//   [8192,12288)  w2 [4096][1024] -> w2T
// ---------------------------------------------------------------------------
__global__ __launch_bounds__(256) void transpose_all(
    const float* __restrict__ wq, const float* __restrict__ wk,
    const float* __restrict__ wv, const float* __restrict__ wo,
    const float* __restrict__ w1, const float* __restrict__ w2,
    __half* __restrict__ wqkvT, __half* __restrict__ woT,
    __half* __restrict__ w1T, __half* __restrict__ w2T)
{
    __shared__ float sh[32][33];
    const int tile = blockIdx.x;
    const float* in;
    __half* out;
    int R, C, cx, ry;
    if (tile < 4096) {
        const int job = tile >> 10, loc = tile & 1023;
        cx = loc & 31; ry = loc >> 5; R = 1024; C = 1024;
        if (job == 0)      { in = wq; out = wqkvT; }
        else if (job == 1) { in = wk; out = wqkvT + (size_t)1024 * 1024; }
        else if (job == 2) { in = wv; out = wqkvT + (size_t)2 * 1024 * 1024; }
        else               { in = wo; out = woT; }
    } else if (tile < 8192) {
        const int loc = tile - 4096;
        cx = loc & 127; ry = loc >> 7; R = 1024; C = 4096;
        in = w1; out = w1T;
    } else {
        const int loc = tile - 8192;
        cx = loc & 31; ry = loc >> 5; R = 4096; C = 1024;
        in = w2; out = w2T;
    }
    const int c0 = cx * 32, r0 = ry * 32;
    const int tx = threadIdx.x, ty = threadIdx.y;
#pragma unroll
    for (int j = 0; j < 4; j++)
        sh[ty + j * 8][tx] = in[(size_t)(r0 + ty + j * 8) * C + c0 + tx];
    __syncthreads();
#pragma unroll
    for (int j = 0; j < 4; j++)
        out[(size_t)(c0 + ty + j * 8) * R + r0 + tx] = __float2half(sh[tx][ty + j * 8]);
}

// ---------------------------------------------------------------------------
// LayerNorm -> fp16 output (feeds GEMM A)
// ---------------------------------------------------------------------------
__global__ __launch_bounds__(256) void ln_kernel(
    const float* __restrict__ x, const float* __restrict__ gam,
    const float* __restrict__ bet, __half* __restrict__ out)
{
    const int row = blockIdx.x;
    const float* xr = x + (size_t)row * DIM;
    float v[4];
    float s = 0.f, ss = 0.f;
#pragma unroll
    for (int i = 0; i < 4; i++) {
        v[i] = xr[threadIdx.x + i * 256];
        s += v[i]; ss += v[i] * v[i];
    }
#pragma unroll
    for (int o = 16; o; o >>= 1) {
        s  += __shfl_xor_sync(0xffffffffu, s, o);
        ss += __shfl_xor_sync(0xffffffffu, ss, o);
    }
    __shared__ float sh1[8], sh2[8];
    const int w = threadIdx.x >> 5, l = threadIdx.x & 31;
    if (l == 0) { sh1[w] = s; sh2[w] = ss; }
    __syncthreads();
    s = 0.f; ss = 0.f;
#pragma unroll
    for (int i = 0; i < 8; i++) { s += sh1[i]; ss += sh2[i]; }
    const float mu   = s * (1.0f / DIM);
    const float var  = ss * (1.0f / DIM) - mu * mu;
    const float rstd = rsqrtf(var + 1e-5f);
    __half* outr = out + (size_t)row * DIM;
#pragma unroll
    for (int i = 0; i < 4; i++) {
        int c = threadIdx.x + i * 256;
        outr[c] = __float2half((v[i] - mu) * rstd * gam[c] + bet[c]);
    }
}

// ---------------------------------------------------------------------------
// Per-position head dots from fp16 qkv: thread t covers 8 channels
// ---------------------------------------------------------------------------
__global__ __launch_bounds__(128) void dots_kernel(
    const __half* __restrict__ qkv, float* __restrict__ dots)
{
    const int row = blockIdx.x;
    const int b = row >> 12, r = row & 4095;
    const int t = threadIdx.x;
    const __half2* qr = (const __half2*)(qkv + (size_t)row * QKVW + 8 * t);
    const __half2* kr = (const __half2*)(qkv + (size_t)row * QKVW + DIM + 8 * t);
    float p = 0.f;
#pragma unroll
    for (int i = 0; i < 4; i++) {
        const float2 a = __half22float2(qr[i]);
        const float2 c = __half22float2(kr[i]);
        p += a.x * c.x + a.y * c.y;
    }
#pragma unroll
    for (int o = 4; o; o >>= 1) p += __shfl_xor_sync(0xffffffffu, p, o);
    if ((t & 7) == 0)
        dots[((size_t)(b * HEADS + (t >> 3))) * SEQ + r] = p * 0.125f;
}

__global__ __launch_bounds__(1024) void softmax_kernel(float* __restrict__ d)
{
    const int row = blockIdx.x;
    float4* p = (float4*)(d + (size_t)row * SEQ);
    float4 v = p[threadIdx.x];
    float m = fmaxf(fmaxf(v.x, v.y), fmaxf(v.z, v.w));
#pragma unroll
    for (int o = 16; o; o >>= 1) m = fmaxf(m, __shfl_xor_sync(0xffffffffu, m, o));
    __shared__ float sm[32];
    const int w = threadIdx.x >> 5, l = threadIdx.x & 31;
    if (l == 0) sm[w] = m;
    __syncthreads();
    m = sm[0];
#pragma unroll
    for (int i = 1; i < 32; i++) m = fmaxf(m, sm[i]);
    __syncthreads();
    float4 e;
    e.x = expf(v.x - m); e.y = expf(v.y - m);
    e.z = expf(v.z - m); e.w = expf(v.w - m);
    float s = e.x + e.y + e.z + e.w;
#pragma unroll
    for (int o = 16; o; o >>= 1) s += __shfl_xor_sync(0xffffffffu, s, o);
    if (l == 0) sm[w] = s;
    __syncthreads();
    s = 0.f;
#pragma unroll
    for (int i = 0; i < 32; i++) s += sm[i];
    const float inv = 1.0f / s;
    e.x *= inv; e.y *= inv; e.z *= inv; e.w *= inv;
    p[threadIdx.x] = e;
}

// attn_out[b,n',c] = att[b, c/64, p(n')] * V[b, p(n'), c]; p(n')=(n'%128)*32+n'/128
__global__ __launch_bounds__(128) void gather_kernel(
    const __half* __restrict__ qkv, const float* __restrict__ att,
    __half* __restrict__ out)
{
    const int nb = blockIdx.x;
    const int b = nb >> 12, n = nb & 4095;
    const int pidx = (n & 127) * 32 + (n >> 7);
    const int t = threadIdx.x;                 // covers channels 8t..8t+7
    const float a = att[((size_t)(b * HEADS + (t >> 3))) * SEQ + pidx];
    const __half2* vv =
        (const __half2*)(qkv + ((size_t)((b << 12) + pidx)) * QKVW + 2 * DIM + 8 * t);
    __half2* o = (__half2*)(out + (size_t)nb * DIM + 8 * t);
#pragma unroll
    for (int i = 0; i < 4; i++) {
        const float2 v = __half22float2(vv[i]);
        o[i] = __floats2half2_rn(a * v.x, a * v.y);
    }
}

// ---------------------------------------------------------------------------
// Launch
// ---------------------------------------------------------------------------
extern "C" void kernel_launch(void* const* d_in, const int* in_sizes, int n_in,
                              void* d_out, int out_size)
{
    const float* x     = (const float*)d_in[0];
    const float* ln1_g = (const float*)d_in[1];
    const float* ln1_b = (const float*)d_in[2];
    const float* wq    = (const float*)d_in[3];
    const float* wk    = (const float*)d_in[4];
    const float* wv    = (const float*)d_in[5];
    const float* wo    = (const float*)d_in[6];
    const float* bo    = (const float*)d_in[7];
    const float* ln2_g = (const float*)d_in[8];
    const float* ln2_b = (const float*)d_in[9];
    const float* w1    = (const float*)d_in[10];
    const float* b1    = (const float*)d_in[11];
    const float* w2    = (const float*)d_in[12];
    const float* b2    = (const float*)d_in[13];
    float* out = (float*)d_out;

    __half *h1, *qkv, *ao, *h2, *act, *wqkvT, *woT, *w1T, *w2T;
    float *x2, *dots;
    cudaGetSymbolAddress((void**)&h1,   g_h1);
    cudaGetSymbolAddress((void**)&qkv,  g_qkv);
    cudaGetSymbolAddress((void**)&ao,   g_ao);
    cudaGetSymbolAddress((void**)&x2,   g_x2);
    cudaGetSymbolAddress((void**)&h2,   g_h2);
    cudaGetSymbolAddress((void**)&dots, g_dot);
    cudaGetSymbolAddress((void**)&act,  g_act);
    cudaGetSymbolAddress((void**)&wqkvT,g_wqkvT);
    cudaGetSymbolAddress((void**)&woT,  g_woT);
    cudaGetSymbolAddress((void**)&w1T,  g_w1T);
    cudaGetSymbolAddress((void**)&w2T,  g_w2T);

    cudaFuncSetAttribute(gemm_fp16<0>, cudaFuncAttributeMaxDynamicSharedMemorySize, SMEM_DYN);
    cudaFuncSetAttribute(gemm_fp16<1>, cudaFuncAttributeMaxDynamicSharedMemorySize, SMEM_DYN);
    cudaFuncSetAttribute(gemm_fp16<2>, cudaFuncAttributeMaxDynamicSharedMemorySize, SMEM_DYN);

    // all 6 weight transposes in one launch (fp16 K-major B operands)
    transpose_all<<<12288, dim3(32, 8)>>>(wq, wk, wv, wo, w1, w2,
                                          wqkvT, woT, w1T, w2T);

    // 1. h1 = LN1(x)  (fp16)
    ln_kernel<<<ROWS, 256>>>(x, ln1_g, ln1_b, h1);
    // 2. qkv = h1 @ [wq|wk|wv]  (fp16 out)
    gemm_fp16<0><<<dim3(QKVW/128, ROWS/128), 128, SMEM_DYN>>>(
        h1, wqkvT, qkv, nullptr, nullptr, ROWS, QKVW, DIM);
    // 3-5. diagonal dots -> softmax over sequence -> permuted gather * V
    dots_kernel<<<ROWS, 128>>>(qkv, dots);
    softmax_kernel<<<BATCH * HEADS, 1024>>>(dots);
    gather_kernel<<<ROWS, 128>>>(qkv, dots, ao);
    // 6. x2 = x + ao @ wo + bo  (fp32 out)
    gemm_fp16<1><<<dim3(DIM/128, ROWS/128), 128, SMEM_DYN>>>(
        ao, woT, x2, x, bo, ROWS, DIM, DIM);
    // 7. h2 = LN2(x2)  (fp16)
    ln_kernel<<<ROWS, 256>>>(x2, ln2_g, ln2_b, h2);
    // 8. act = gelu(h2 @ w1 + b1)  (fp16 out)
    gemm_fp16<2><<<dim3(DFF/128, ROWS/128), 128, SMEM_DYN>>>(
        h2, w1T, act, nullptr, b1, ROWS, DFF, DIM);
    // 9. out = x2 + act @ w2 + b2  (fp32 out)
    gemm_fp16<1><<<dim3(DIM/128, ROWS/128), 128, SMEM_DYN>>>(
        act, w2T, out, x2, b2, ROWS, DIM, DFF);
}

// round 9
// speedup vs baseline: 1.1764x; 1.1764x over previous
#include <cuda_runtime.h>
#include <cuda_fp16.h>
#include <math.h>
#include <stdint.h>

// Problem dims (fixed)
#define BATCH 4
#define SEQ   4096
#define DIM   1024
#define HEADS 16
#define DFF   4096
#define ROWS  16384
#define QKVW  3072

// ---------------------------------------------------------------------------
// Scratch (device globals; no runtime allocation allowed)
// ---------------------------------------------------------------------------
__device__ __half g_h1  [ROWS*(size_t)DIM];
__device__ __half g_qkv [ROWS*(size_t)QKVW];
__device__ __half g_ao  [ROWS*(size_t)DIM];
__device__ float  g_x2  [ROWS*(size_t)DIM];
__device__ __half g_h2  [ROWS*(size_t)DIM];
__device__ float  g_dot [BATCH*HEADS*(size_t)SEQ];
__device__ __half g_act [ROWS*(size_t)DFF];
__device__ __half g_wqkvT[(size_t)QKVW*DIM];   // [3072][1024] K-major (N rows)
__device__ __half g_woT [(size_t)DIM*DIM];
__device__ __half g_w1T [(size_t)DFF*DIM];
__device__ __half g_w2T [(size_t)DIM*DFF];

// ---------------------------------------------------------------------------
// Helpers
// ---------------------------------------------------------------------------
__device__ __forceinline__ float gelu_exact(float x) {
    return 0.5f * x * (1.0f + erff(x * 0.70710678118654752f));
}
__device__ __forceinline__ uint32_t smem_u32(const void* p) {
    uint32_t a;
    asm("{ .reg .u64 t; cvta.to.shared.u64 t, %1; cvt.u32.u64 %0, t; }"
        : "=r"(a) : "l"(p));
    return a;
}
__device__ __forceinline__ void cp16(uint32_t dst, const void* src) {
    asm volatile("cp.async.cg.shared.global [%0], [%1], 16;" :: "r"(dst), "l"(src));
}
__device__ __forceinline__ void cp_commit() {
    asm volatile("cp.async.commit_group;" ::: "memory");
}
#define LDMX4(r0, r1, r2, r3, addr)                                           \
    asm volatile("ldmatrix.sync.aligned.m8n8.x4.shared.b16 {%0,%1,%2,%3}, [%4];" \
        : "=r"(r0), "=r"(r1), "=r"(r2), "=r"(r3) : "r"(addr))

// smem row: 32 k-halves data + 8 pad halves -> stride 40 halves (80B).
// Rows r within an 8-row ldmatrix tile hit banks (r*20)%32: all distinct.
#define OP_B     10240                     // bytes per operand tile (128*80)
#define STAGE_B  (2*OP_B)                  // 20480
#define STAGES   4
#define SMEM_DYN (STAGES*STAGE_B)          // 81920

// ---------------------------------------------------------------------------
// FP16 tensor-core GEMM: C[M,N] = A[M,K] @ Bt[N,K]^T  (A,Bt fp16)
//  EPI 0: store half           (C = __half*)
//  EPI 1: float store +res+bias (C = float*, res fp32)
//  EPI 2: half store gelu(+bias)
// CTA 128x128, 128 threads (4 warps 2x2, warp tile 64x64), k-chunk 32,
// 4-stage cp.async pipeline, ldmatrix fragment loads.  (R5-proven config.)
// ---------------------------------------------------------------------------
template <int EPI>
__global__ __launch_bounds__(128, 2) void gemm_fp16(
    const __half* __restrict__ A, const __half* __restrict__ Bt,
    void* __restrict__ Cv, const float* __restrict__ res,
    const float* __restrict__ bias, int M, int N, int K)
{
    extern __shared__ char smc[];
    const uint32_t smb = smem_u32(smc);

    const int tid  = threadIdx.x;
    const int lane = tid & 31;
    const int wid  = tid >> 5;
    const int wm   = wid >> 1;
    const int wn   = wid & 1;
    const int g    = lane >> 2;
    const int t    = lane & 3;
    const int m0   = blockIdx.y << 7;
    const int n0   = blockIdx.x << 7;

    // ldmatrix per-lane base offsets (bytes within stage)
    // A tiles: lanes 0-7:(r,k0) 8-15:(r+8,k0) 16-23:(r,k8) 24-31:(r+8,k8)
    const uint32_t aoff =
        (uint32_t)(((wm * 64 + (lane & 7) + 8 * ((lane >> 3) & 1)) * 40 +
                    8 * (lane >> 4)) * 2);
    // B tiles: lanes 0-7:(n,k0) 8-15:(n,k8) 16-23:(n+8,k0) 24-31:(n+8,k8)
    const uint32_t boff =
        (uint32_t)(OP_B + (((wn * 64 + (lane & 7) + 8 * (lane >> 4)) * 40 +
                            8 * ((lane >> 3) & 1)) * 2));

    // staging: per operand 512 granules of 16B; 4 per thread
    uint32_t sA[4], sB[4];
    const __half* gA[4];
    const __half* gB[4];
#pragma unroll
    for (int j = 0; j < 4; j++) {
        const int gid = j * 128 + tid;
        const int row = gid >> 2, c = gid & 3;
        sA[j] = (uint32_t)(row * 80 + c * 16);
        sB[j] = (uint32_t)(OP_B + row * 80 + c * 16);
        gA[j] = A  + (size_t)(m0 + row) * K + c * 8;
        gB[j] = Bt + (size_t)(n0 + row) * K + c * 8;
    }

    float acc[4][8][4];
#pragma unroll
    for (int i = 0; i < 4; i++)
#pragma unroll
        for (int j = 0; j < 8; j++)
#pragma unroll
            for (int r = 0; r < 4; r++) acc[i][j][r] = 0.f;

    const int KT = K >> 5;

#pragma unroll
    for (int s = 0; s < STAGES; s++) {
        const uint32_t base = smb + s * STAGE_B;
        const int ko = s * 32;
#pragma unroll
        for (int j = 0; j < 4; j++) {
            cp16(base + sA[j], gA[j] + ko);
            cp16(base + sB[j], gB[j] + ko);
        }
        cp_commit();
    }

    for (int kt = 0; kt < KT; kt++) {
        asm volatile("cp.async.wait_group %0;" :: "n"(STAGES - 1) : "memory");
        __syncthreads();

        const uint32_t stg = smb + (kt % STAGES) * STAGE_B;

#pragma unroll
        for (int kc = 0; kc < 2; kc++) {
            const uint32_t kb = kc * 32;            // 16 halves
            uint32_t af[4][4];
#pragma unroll
            for (int i = 0; i < 4; i++)
                LDMX4(af[i][0], af[i][1], af[i][2], af[i][3],
                      stg + aoff + i * 1280 + kb);
            uint32_t bf[8][2];
#pragma unroll
            for (int jj = 0; jj < 4; jj++)
                LDMX4(bf[2 * jj][0], bf[2 * jj][1],
                      bf[2 * jj + 1][0], bf[2 * jj + 1][1],
                      stg + boff + jj * 1280 + kb);
#pragma unroll
            for (int i = 0; i < 4; i++)
#pragma unroll
                for (int j = 0; j < 8; j++) {
                    asm volatile(
                        "mma.sync.aligned.m16n8k16.row.col.f32.f16.f16.f32 "
                        "{%0,%1,%2,%3}, {%4,%5,%6,%7}, {%8,%9}, {%0,%1,%2,%3};"
                        : "+f"(acc[i][j][0]), "+f"(acc[i][j][1]),
                          "+f"(acc[i][j][2]), "+f"(acc[i][j][3])
                        : "r"(af[i][0]), "r"(af[i][1]),
                          "r"(af[i][2]), "r"(af[i][3]),
                          "r"(bf[j][0]), "r"(bf[j][1]));
                }
        }
        __syncthreads();

        const int nk = kt + STAGES;
        if (nk < KT) {
            const uint32_t base = smb + (nk % STAGES) * STAGE_B;
            const int ko = nk * 32;
#pragma unroll
            for (int j = 0; j < 4; j++) {
                cp16(base + sA[j], gA[j] + ko);
                cp16(base + sB[j], gB[j] + ko);
            }
        }
        cp_commit();
    }

    // epilogue
#pragma unroll
    for (int j = 0; j < 8; j++) {
        const int col = n0 + wn * 64 + j * 8 + t * 2;
        float2 bv = make_float2(0.f, 0.f);
        if (EPI != 0) bv = *(const float2*)&bias[col];
#pragma unroll
        for (int i = 0; i < 4; i++) {
            const int row0 = m0 + wm * 64 + i * 16 + g;
#pragma unroll
            for (int h = 0; h < 2; h++) {
                const int r = row0 + 8 * h;
                const float a = acc[i][j][2 * h + 0];
                const float b = acc[i][j][2 * h + 1];
                if (EPI == 0) {
                    *(__half2*)((__half*)Cv + (size_t)r * N + col) =
                        __floats2half2_rn(a, b);
                } else if (EPI == 1) {
                    const float2 rv = *(const float2*)&res[(size_t)r * N + col];
                    float2 o;
                    o.x = a + rv.x + bv.x;
                    o.y = b + rv.y + bv.y;
                    *(float2*)((float*)Cv + (size_t)r * N + col) = o;
                } else {
                    *(__half2*)((__half*)Cv + (size_t)r * N + col) =
                        __floats2half2_rn(gelu_exact(a + bv.x),
                                          gelu_exact(b + bv.y));
                }
            }
        }
    }
}

// ---------------------------------------------------------------------------
// All 6 weight transposes in ONE launch. Tile t:
//   [0,4096)      4 square jobs wq/wk/wv/wo  (1024x1024, 32x32 grids)
//   [4096,8192)   w1 [1024][4096] -> w1T
//   [8192,12288)  w2 [4096][1024] -> w2T
// ---------------------------------------------------------------------------
__global__ __launch_bounds__(256) void transpose_all(
    const float* __restrict__ wq, const float* __restrict__ wk,
    const float* __restrict__ wv, const float* __restrict__ wo,
    const float* __restrict__ w1, const float* __restrict__ w2,
    __half* __restrict__ wqkvT, __half* __restrict__ woT,
    __half* __restrict__ w1T, __half* __restrict__ w2T)
{
    __shared__ float sh[32][33];
    const int tile = blockIdx.x;
    const float* in;
    __half* out;
    int R, C, cx, ry;
    if (tile < 4096) {
        const int job = tile >> 10, loc = tile & 1023;
        cx = loc & 31; ry = loc >> 5; R = 1024; C = 1024;
        if (job == 0)      { in = wq; out = wqkvT; }
        else if (job == 1) { in = wk; out = wqkvT + (size_t)1024 * 1024; }
        else if (job == 2) { in = wv; out = wqkvT + (size_t)2 * 1024 * 1024; }
        else               { in = wo; out = woT; }
    } else if (tile < 8192) {
        const int loc = tile - 4096;
        cx = loc & 127; ry = loc >> 7; R = 1024; C = 4096;
        in = w1; out = w1T;
    } else {
        const int loc = tile - 8192;
        cx = loc & 31; ry = loc >> 5; R = 4096; C = 1024;
        in = w2; out = w2T;
    }
    const int c0 = cx * 32, r0 = ry * 32;
    const int tx = threadIdx.x, ty = threadIdx.y;
#pragma unroll
    for (int j = 0; j < 4; j++)
        sh[ty + j * 8][tx] = in[(size_t)(r0 + ty + j * 8) * C + c0 + tx];
    __syncthreads();
#pragma unroll
    for (int j = 0; j < 4; j++)
        out[(size_t)(c0 + ty + j * 8) * R + r0 + tx] = __float2half(sh[tx][ty + j * 8]);
}

// ---------------------------------------------------------------------------
// LayerNorm -> fp16 output (feeds GEMM A)
// ---------------------------------------------------------------------------
__global__ __launch_bounds__(256) void ln_kernel(
    const float* __restrict__ x, const float* __restrict__ gam,
    const float* __restrict__ bet, __half* __restrict__ out)
{
    const int row = blockIdx.x;
    const float* xr = x + (size_t)row * DIM;
    float v[4];
    float s = 0.f, ss = 0.f;
#pragma unroll
    for (int i = 0; i < 4; i++) {
        v[i] = xr[threadIdx.x + i * 256];
        s += v[i]; ss += v[i] * v[i];
    }
#pragma unroll
    for (int o = 16; o; o >>= 1) {
        s  += __shfl_xor_sync(0xffffffffu, s, o);
        ss += __shfl_xor_sync(0xffffffffu, ss, o);
    }
    __shared__ float sh1[8], sh2[8];
    const int w = threadIdx.x >> 5, l = threadIdx.x & 31;
    if (l == 0) { sh1[w] = s; sh2[w] = ss; }
    __syncthreads();
    s = 0.f; ss = 0.f;
#pragma unroll
    for (int i = 0; i < 8; i++) { s += sh1[i]; ss += sh2[i]; }
    const float mu   = s * (1.0f / DIM);
    const float var  = ss * (1.0f / DIM) - mu * mu;
    const float rstd = rsqrtf(var + 1e-5f);
    __half* outr = out + (size_t)row * DIM;
#pragma unroll
    for (int i = 0; i < 4; i++) {
        int c = threadIdx.x + i * 256;
        outr[c] = __float2half((v[i] - mu) * rstd * gam[c] + bet[c]);
    }
}

// ---------------------------------------------------------------------------
// Per-position head dots from fp16 qkv: thread t covers 8 channels
// ---------------------------------------------------------------------------
__global__ __launch_bounds__(128) void dots_kernel(
    const __half* __restrict__ qkv, float* __restrict__ dots)
{
    const int row = blockIdx.x;
    const int b = row >> 12, r = row & 4095;
    const int t = threadIdx.x;
    const __half2* qr = (const __half2*)(qkv + (size_t)row * QKVW + 8 * t);
    const __half2* kr = (const __half2*)(qkv + (size_t)row * QKVW + DIM + 8 * t);
    float p = 0.f;
#pragma unroll
    for (int i = 0; i < 4; i++) {
        const float2 a = __half22float2(qr[i]);
        const float2 c = __half22float2(kr[i]);
        p += a.x * c.x + a.y * c.y;
    }
#pragma unroll
    for (int o = 4; o; o >>= 1) p += __shfl_xor_sync(0xffffffffu, p, o);
    if ((t & 7) == 0)
        dots[((size_t)(b * HEADS + (t >> 3))) * SEQ + r] = p * 0.125f;
}

__global__ __launch_bounds__(1024) void softmax_kernel(float* __restrict__ d)
{
    const int row = blockIdx.x;
    float4* p = (float4*)(d + (size_t)row * SEQ);
    float4 v = p[threadIdx.x];
    float m = fmaxf(fmaxf(v.x, v.y), fmaxf(v.z, v.w));
#pragma unroll
    for (int o = 16; o; o >>= 1) m = fmaxf(m, __shfl_xor_sync(0xffffffffu, m, o));
    __shared__ float sm[32];
    const int w = threadIdx.x >> 5, l = threadIdx.x & 31;
    if (l == 0) sm[w] = m;
    __syncthreads();
    m = sm[0];
#pragma unroll
    for (int i = 1; i < 32; i++) m = fmaxf(m, sm[i]);
    __syncthreads();
    float4 e;
    e.x = expf(v.x - m); e.y = expf(v.y - m);
    e.z = expf(v.z - m); e.w = expf(v.w - m);
    float s = e.x + e.y + e.z + e.w;
#pragma unroll
    for (int o = 16; o; o >>= 1) s += __shfl_xor_sync(0xffffffffu, s, o);
    if (l == 0) sm[w] = s;
    __syncthreads();
    s = 0.f;
#pragma unroll
    for (int i = 0; i < 32; i++) s += sm[i];
    const float inv = 1.0f / s;
    e.x *= inv; e.y *= inv; e.z *= inv; e.w *= inv;
    p[threadIdx.x] = e;
}

// attn_out[b,n',c] = att[b, c/64, p(n')] * V[b, p(n'), c]; p(n')=(n'%128)*32+n'/128
__global__ __launch_bounds__(128) void gather_kernel(
    const __half* __restrict__ qkv, const float* __restrict__ att,
    __half* __restrict__ out)
{
    const int nb = blockIdx.x;
    const int b = nb >> 12, n = nb & 4095;
    const int pidx = (n & 127) * 32 + (n >> 7);
    const int t = threadIdx.x;                 // covers channels 8t..8t+7
    const float a = att[((size_t)(b * HEADS + (t >> 3))) * SEQ + pidx];
    const __half2* vv =
        (const __half2*)(qkv + ((size_t)((b << 12) + pidx)) * QKVW + 2 * DIM + 8 * t);
    __half2* o = (__half2*)(out + (size_t)nb * DIM + 8 * t);
#pragma unroll
    for (int i = 0; i < 4; i++) {
        const float2 v = __half22float2(vv[i]);
        o[i] = __floats2half2_rn(a * v.x, a * v.y);
    }
}

// ---------------------------------------------------------------------------
// Launch
// ---------------------------------------------------------------------------
extern "C" void kernel_launch(void* const* d_in, const int* in_sizes, int n_in,
                              void* d_out, int out_size)
{
    const float* x     = (const float*)d_in[0];
    const float* ln1_g = (const float*)d_in[1];
    const float* ln1_b = (const float*)d_in[2];
    const float* wq    = (const float*)d_in[3];
    const float* wk    = (const float*)d_in[4];
    const float* wv    = (const float*)d_in[5];
    const float* wo    = (const float*)d_in[6];
    const float* bo    = (const float*)d_in[7];
    const float* ln2_g = (const float*)d_in[8];
    const float* ln2_b = (const float*)d_in[9];
    const float* w1    = (const float*)d_in[10];
    const float* b1    = (const float*)d_in[11];
    const float* w2    = (const float*)d_in[12];
    const float* b2    = (const float*)d_in[13];
    float* out = (float*)d_out;

    __half *h1, *qkv, *ao, *h2, *act, *wqkvT, *woT, *w1T, *w2T;
    float *x2, *dots;
    cudaGetSymbolAddress((void**)&h1,   g_h1);
    cudaGetSymbolAddress((void**)&qkv,  g_qkv);
    cudaGetSymbolAddress((void**)&ao,   g_ao);
    cudaGetSymbolAddress((void**)&x2,   g_x2);
    cudaGetSymbolAddress((void**)&h2,   g_h2);
    cudaGetSymbolAddress((void**)&dots, g_dot);
    cudaGetSymbolAddress((void**)&act,  g_act);
    cudaGetSymbolAddress((void**)&wqkvT,g_wqkvT);
    cudaGetSymbolAddress((void**)&woT,  g_woT);
    cudaGetSymbolAddress((void**)&w1T,  g_w1T);
    cudaGetSymbolAddress((void**)&w2T,  g_w2T);

    cudaFuncSetAttribute(gemm_fp16<0>, cudaFuncAttributeMaxDynamicSharedMemorySize, SMEM_DYN);
    cudaFuncSetAttribute(gemm_fp16<1>, cudaFuncAttributeMaxDynamicSharedMemorySize, SMEM_DYN);
    cudaFuncSetAttribute(gemm_fp16<2>, cudaFuncAttributeMaxDynamicSharedMemorySize, SMEM_DYN);

    // all 6 weight transposes in one launch (fp16 K-major B operands)
    transpose_all<<<12288, dim3(32, 8)>>>(wq, wk, wv, wo, w1, w2,
                                          wqkvT, woT, w1T, w2T);

    // 1. h1 = LN1(x)  (fp16)
    ln_kernel<<<ROWS, 256>>>(x, ln1_g, ln1_b, h1);
    // 2. qkv = h1 @ [wq|wk|wv]  (fp16 out)
    gemm_fp16<0><<<dim3(QKVW/128, ROWS/128), 128, SMEM_DYN>>>(
        h1, wqkvT, qkv, nullptr, nullptr, ROWS, QKVW, DIM);
    // 3-5. diagonal dots -> softmax over sequence -> permuted gather * V
    dots_kernel<<<ROWS, 128>>>(qkv, dots);
    softmax_kernel<<<BATCH * HEADS, 1024>>>(dots);
    gather_kernel<<<ROWS, 128>>>(qkv, dots, ao);
    // 6. x2 = x + ao @ wo + bo  (fp32 out)
    gemm_fp16<1><<<dim3(DIM/128, ROWS/128), 128, SMEM_DYN>>>(
        ao, woT, x2, x, bo, ROWS, DIM, DIM);
    // 7. h2 = LN2(x2)  (fp16)
    ln_kernel<<<ROWS, 256>>>(x2, ln2_g, ln2_b, h2);
    // 8. act = gelu(h2 @ w1 + b1)  (fp16 out)
    gemm_fp16<2><<<dim3(DFF/128, ROWS/128), 128, SMEM_DYN>>>(
        h2, w1T, act, nullptr, b1, ROWS, DFF, DIM);
    // 9. out = x2 + act @ w2 + b2  (fp32 out)
    gemm_fp16<1><<<dim3(DIM/128, ROWS/128), 128, SMEM_DYN>>>(
        act, w2T, out, x2, b2, ROWS, DIM, DFF);
}